// round 15
// baseline (speedup 1.0000x reference)
#include <cuda_runtime.h>

// Problem constants (fixed instance: MultiHeadAggregator_55825984913801)
#define L_    12     // layers used (hidden_states[1:])
#define B_    8
#define T_    2048
#define H_    768
#define C_    4
#define MAXNT 160    // max masked positions supported (expected: hte<=5, desc~12)
#define RCACHE 24    // rows cached in smem (fallback to global reads beyond)
#define TPB   256
#define TOKS_PER_THR (T_ / TPB)   // 8
#define NDMAX 3
#define NJ    (H_ / 4 / 16)       // 12 float4 loads per 16-lane row task

// Cross-block handshake (zero-init; self-resetting per graph replay).
__device__ volatile int g_ready[2 * B_];
__device__ int          g_cnt[2 * B_];

// ---------------------------------------------------------------------------
// SINGLE node: one block per (b, mt, l).
//  - the l==0 block of each bm zeroes its 12 KB out-slice FIRST (harness
//    poisons d_out; previous replay's values persist otherwise), fences,
//    and raises g_ready[bm]; other blocks only check the flag right before
//    their REDs (by then it is long set -> expected wait ~0).
//  - deadlock-safe: 84 KB smem / 118 regs -> 2 blocks/SM -> all 192 blocks
//    co-resident, so the zeroing block always runs.
//  - epoch 1: ALL independent loads; deterministic mask compaction;
//    MLP=12 staged gather with smem row cache; warp-parallel softmax;
//    RED.ADD straight into d_out (no g_accum, no tail copy).
//  - 12th arrival per bm resets flag+counter for the next replay.
// Only masked positions contribute: -1e30 masking + fp32 softmax zeroes all
// other positions exactly, so the dense reference reduces to this sparse form.
// ---------------------------------------------------------------------------
__global__ __launch_bounds__(TPB, 1)
void fused_kernel(const float* __restrict__ hidden,      // (L_+1, B, T, H)
                  const float* __restrict__ scorer_w,    // (C, H)
                  const float* __restrict__ layer_logits,// (L_)
                  const int*   __restrict__ ids32,
                  const int*   __restrict__ hte_ptr,     // low 4B of scalar
                  const int*   __restrict__ win_ptr,     // low 4B of scalar
                  const int*   __restrict__ dtok32,
                  int n_d,
                  float* __restrict__ out) {             // (B, 2, C, H)
    const int l  = blockIdx.x;          // 0..L_-1
    const int bm = blockIdx.y;          // 0..2*B_-1  (== b*2 + mt)
    const int b  = bm >> 1;
    const int mt = bm & 1;
    const int tid  = threadIdx.x;
    const int wid  = tid >> 5, lane = tid & 31;

    extern __shared__ char dsm[];
    float4* s_sc4  = (float4*)dsm;                         // 12 KB scorer
    float*  s_rows = (float*)(dsm + C_ * (H_ / 4) * 16);   // RCACHE x 768 f32

    __shared__ float  s_s[MAXNT][C_];
    __shared__ int    s_idx[MAXNT];
    __shared__ int    s_nt;
    __shared__ int    s_notzero, s_min;
    __shared__ int    s_wsum[TPB / 32], s_woff[TPB / 32];
    __shared__ float  s_lw;
    __shared__ int    s_hte, s_win;
    __shared__ int    s_d[2][NDMAX];     // dtok under stride-1 / stride-2 hypotheses

    float* op = out + (size_t)bm * (C_ * H_);

    if (tid == 0) { s_notzero = 0; s_min = 0x7fffffff; }
    __syncthreads();

    // ---- l==0 blocks: zero this bm's out-slice immediately, raise flag -----
    if (l == 0) {
        float4* op4 = (float4*)op;
        #pragma unroll
        for (int r = 0; r < 3; r++)                     // 3*256 = 768 float4
            op4[r * TPB + tid] = make_float4(0.f, 0.f, 0.f, 0.f);
        __syncthreads();
        if (tid == 0) {
            __threadfence();                            // publish zeros
            g_ready[bm] = 1;                            // release
        }
    }

    // ================= EPOCH 1: all independent loads =======================
    {   // scorer weights to smem
        const float4* sw4 = (const float4*)scorer_w;
        for (int i = tid; i < C_ * (H_ / 4); i += TPB) s_sc4[i] = sw4[i];
    }
    // speculative stride-1 token scan: 2 coalesced int4 loads per thread
    // (in-bounds under both dtype hypotheses)
    int myids[TOKS_PER_THR];
    {
        const int4* row4 = (const int4*)(ids32 + (size_t)b * T_);
        int4 v0 = row4[tid * 2];
        int4 v1 = row4[tid * 2 + 1];
        myids[0] = v0.x; myids[1] = v0.y; myids[2] = v0.z; myids[3] = v0.w;
        myids[4] = v1.x; myids[5] = v1.y; myids[6] = v1.z; myids[7] = v1.w;
    }
    if (tid < 128 && ids32[2 * tid + 1] != 0) atomicOr(&s_notzero, 1);
    if (tid == 4) s_hte = *hte_ptr;
    if (tid == 5) s_win = *win_ptr;
    if (tid >= 8  && tid < 8 + NDMAX) {           // stride-1 hypothesis
        int k = tid - 8;
        s_d[0][k] = (k < n_d) ? dtok32[k] : 0x7fffffff;
    }
    if (tid >= 12 && tid < 12 + NDMAX) {          // stride-2 hypothesis
        int k = tid - 12;
        s_d[1][k] = (k < n_d) ? dtok32[2 * k] : 0x7fffffff;
    }
    if (tid == 0) {   // layer softmax (12 elems)
        float m = -1e30f;
        #pragma unroll
        for (int k = 0; k < L_; k++) m = fmaxf(m, layer_logits[k]);
        float s = 0.f, el = 0.f;
        #pragma unroll
        for (int k = 0; k < L_; k++) {
            float e = __expf(layer_logits[k] - m);
            s += e;
            if (k == l) el = e;
        }
        s_lw = el / s;
    }
    __syncthreads();

    const int st = s_notzero ? 1 : 2;
    const int hy = s_notzero ? 0 : 1;
    if (st == 2) {  // rare path: buffer was int64 -> re-load tokens at stride 2
        const int* row2 = ids32 + (size_t)b * T_ * 2;
        #pragma unroll
        for (int j = 0; j < TOKS_PER_THR; j++)
            myids[j] = row2[(size_t)(tid * TOKS_PER_THR + j) * 2];
    }
    const int hte = s_hte;

    // ---- build mask index list for (b, mt), deterministic ------------------
    if (mt == 0) {
        int local = 0x7fffffff;
        #pragma unroll
        for (int j = 0; j < TOKS_PER_THR; j++)
            if (myids[j] == hte) local = min(local, tid * TOKS_PER_THR + j);
        if (local != 0x7fffffff) atomicMin(&s_min, local);
        __syncthreads();
        if (tid == 0) {
            int pos = (s_min == 0x7fffffff) ? (T_ - 1) : s_min;
            int hi  = pos + s_win;
            if (hi > T_ - 1) hi = T_ - 1;
            int cnt = hi - pos + 1;
            if (cnt > MAXNT) cnt = MAXNT;
            s_nt = cnt;
            for (int i = 0; i < cnt; i++) s_idx[i] = pos + i;
        }
        __syncthreads();
    } else {
        const int d0 = s_d[hy][0], d1 = s_d[hy][1], d2 = s_d[hy][2];
        int cnt = 0, loc[TOKS_PER_THR];
        #pragma unroll
        for (int j = 0; j < TOKS_PER_THR; j++) {
            int id = myids[j];
            bool isd = (id == d0) | (id == d1) | (id == d2);
            for (int k = NDMAX; k < n_d; k++) isd |= (id == dtok32[k * st]);
            if (isd) loc[cnt++] = tid * TOKS_PER_THR + j;
        }
        int inc = cnt;
        #pragma unroll
        for (int o = 1; o < 32; o <<= 1) {
            int y = __shfl_up_sync(0xffffffffu, inc, o);
            if (lane >= o) inc += y;
        }
        if (lane == 31) s_wsum[wid] = inc;
        __syncthreads();
        if (tid == 0) {
            int acc = 0;
            #pragma unroll
            for (int w = 0; w < TPB / 32; w++) { s_woff[w] = acc; acc += s_wsum[w]; }
            int total = acc;
            if (total == 0) { s_idx[0] = 0; total = 1; }
            s_nt = (total > MAXNT) ? MAXNT : total;
        }
        __syncthreads();
        int off = s_woff[wid] + inc - cnt;   // exclusive prefix
        for (int k = 0; k < cnt; k++)
            if (off + k < MAXNT) s_idx[off + k] = loc[k];
        __syncthreads();
    }
    const int nt = s_nt;

    // ================= EPOCH 2: gather, 16-lane row tasks ====================
    // Load-all-then-compute: 12 float4 staged in registers (MLP=12 -> one
    // latency epoch). Half-warp shuffle masks keep odd-nt convergence legal.
    const float*  hbase_f = hidden + (((size_t)(l + 1) * B_ + b) * T_) * H_;
    const float4* hbase   = (const float4*)hbase_f;
    {
        const int task = tid >> 4, l16 = tid & 15;         // 16 tasks x 16 lanes
        const unsigned hmask = 0xFFFFu << (lane & 16);      // my half-warp
        for (int ti = task; ti < nt; ti += 16) {
            const float4* hp = hbase + (size_t)s_idx[ti] * (H_ / 4);
            float4 xs[NJ];
            #pragma unroll
            for (int j = 0; j < NJ; j++) xs[j] = hp[j * 16 + l16];   // 12 LDG in flight
            if (ti < RCACHE) {
                float4* cache4 = (float4*)(s_rows + ti * H_);
                #pragma unroll
                for (int j = 0; j < NJ; j++) cache4[j * 16 + l16] = xs[j];
            }
            float a0 = 0.f, a1 = 0.f, a2 = 0.f, a3 = 0.f;
            #pragma unroll
            for (int j = 0; j < NJ; j++) {
                int idx = j * 16 + l16;
                float4 x  = xs[j];
                float4 w0 = s_sc4[0 * (H_ / 4) + idx];
                float4 w1 = s_sc4[1 * (H_ / 4) + idx];
                float4 w2 = s_sc4[2 * (H_ / 4) + idx];
                float4 w3 = s_sc4[3 * (H_ / 4) + idx];
                a0 = fmaf(x.x, w0.x, fmaf(x.y, w0.y, fmaf(x.z, w0.z, fmaf(x.w, w0.w, a0))));
                a1 = fmaf(x.x, w1.x, fmaf(x.y, w1.y, fmaf(x.z, w1.z, fmaf(x.w, w1.w, a1))));
                a2 = fmaf(x.x, w2.x, fmaf(x.y, w2.y, fmaf(x.z, w2.z, fmaf(x.w, w2.w, a2))));
                a3 = fmaf(x.x, w3.x, fmaf(x.y, w3.y, fmaf(x.z, w3.z, fmaf(x.w, w3.w, a3))));
            }
            #pragma unroll
            for (int o = 8; o; o >>= 1) {                  // reduce within half-warp
                a0 += __shfl_xor_sync(hmask, a0, o);
                a1 += __shfl_xor_sync(hmask, a1, o);
                a2 += __shfl_xor_sync(hmask, a2, o);
                a3 += __shfl_xor_sync(hmask, a3, o);
            }
            if (l16 == 0) {
                s_s[ti][0] = a0; s_s[ti][1] = a1; s_s[ti][2] = a2; s_s[ti][3] = a3;
            }
        }
    }
    __syncthreads();

    // ---- warp-parallel softmax: warp c per channel, lanes over positions ----
    if (wid < C_) {
        const int c = wid;
        float m = -1e30f;
        for (int i = lane; i < nt; i += 32) m = fmaxf(m, s_s[i][c]);
        #pragma unroll
        for (int o = 16; o; o >>= 1) m = fmaxf(m, __shfl_xor_sync(0xffffffffu, m, o));
        float s = 0.f;
        for (int i = lane; i < nt; i += 32) {
            float e = __expf(s_s[i][c] - m);
            s_s[i][c] = e; s += e;
        }
        #pragma unroll
        for (int o = 16; o; o >>= 1) s += __shfl_xor_sync(0xffffffffu, s, o);
        float inv = s_lw / s;
        for (int i = lane; i < nt; i += 32) s_s[i][c] *= inv;
    }

    // ---- wait for the zeroing flag (expected already set) -------------------
    __syncthreads();
    if (tid == 0) {
        while (g_ready[bm] == 0) { }        // l==0 raised it ~1 us ago
    }
    __syncthreads();                        // all threads see the zeros (acquire via fence+flag)

    // ---- this layer's contribution: RED.ADD straight into d_out ------------
    if (tid < H_ / 4) {                     // 192 threads, one float4 column each
        const int h0 = tid * 4;
        float4 a0 = {0,0,0,0}, a1 = {0,0,0,0}, a2 = {0,0,0,0}, a3 = {0,0,0,0};
        for (int i = 0; i < nt; i++) {
            float4 x = (i < RCACHE) ? *(const float4*)&s_rows[i * H_ + h0]
                                    : *(const float4*)&hbase_f[(size_t)s_idx[i] * H_ + h0];
            float w0 = s_s[i][0], w1 = s_s[i][1], w2 = s_s[i][2], w3 = s_s[i][3];
            a0.x = fmaf(w0, x.x, a0.x); a0.y = fmaf(w0, x.y, a0.y); a0.z = fmaf(w0, x.z, a0.z); a0.w = fmaf(w0, x.w, a0.w);
            a1.x = fmaf(w1, x.x, a1.x); a1.y = fmaf(w1, x.y, a1.y); a1.z = fmaf(w1, x.z, a1.z); a1.w = fmaf(w1, x.w, a1.w);
            a2.x = fmaf(w2, x.x, a2.x); a2.y = fmaf(w2, x.y, a2.y); a2.z = fmaf(w2, x.z, a2.z); a2.w = fmaf(w2, x.w, a2.w);
            a3.x = fmaf(w3, x.x, a3.x); a3.y = fmaf(w3, x.y, a3.y); a3.z = fmaf(w3, x.z, a3.z); a3.w = fmaf(w3, x.w, a3.w);
        }
        atomicAdd(&op[0 * H_ + h0 + 0], a0.x); atomicAdd(&op[0 * H_ + h0 + 1], a0.y);
        atomicAdd(&op[0 * H_ + h0 + 2], a0.z); atomicAdd(&op[0 * H_ + h0 + 3], a0.w);
        atomicAdd(&op[1 * H_ + h0 + 0], a1.x); atomicAdd(&op[1 * H_ + h0 + 1], a1.y);
        atomicAdd(&op[1 * H_ + h0 + 2], a1.z); atomicAdd(&op[1 * H_ + h0 + 3], a1.w);
        atomicAdd(&op[2 * H_ + h0 + 0], a2.x); atomicAdd(&op[2 * H_ + h0 + 1], a2.y);
        atomicAdd(&op[2 * H_ + h0 + 2], a2.z); atomicAdd(&op[2 * H_ + h0 + 3], a2.w);
        atomicAdd(&op[3 * H_ + h0 + 0], a3.x); atomicAdd(&op[3 * H_ + h0 + 1], a3.y);
        atomicAdd(&op[3 * H_ + h0 + 2], a3.z); atomicAdd(&op[3 * H_ + h0 + 3], a3.w);
    }

    // ---- self-reset for the next graph replay ------------------------------
    __syncthreads();                        // my REDs issued
    if (tid == 0) {
        int old = atomicAdd(&g_cnt[bm], 1);
        if (old == L_ - 1) {                // 12th arrival: everyone passed the spin
            g_cnt[bm] = 0;
            g_ready[bm] = 0;
        }
    }
}

// ---------------------------------------------------------------------------
extern "C" void kernel_launch(void* const* d_in, const int* in_sizes, int n_in,
                              void* d_out, int out_size) {
    const float* hidden = (const float*)d_in[0];
    const int*   ids    = (const int*)d_in[1];
    const float* logits = (const float*)d_in[2];
    const float* scorer = (const float*)d_in[3];
    const int*   hte    = (const int*)d_in[4];   // low 4B valid for i32/i64 small values
    const int*   dtok   = (const int*)d_in[5];
    const int*   win    = (const int*)d_in[6];
    const int n_d = in_sizes[5];

    const int dyn_smem = C_ * (H_ / 4) * 16 + RCACHE * H_ * 4;  // 12 KB + 72 KB
    cudaFuncSetAttribute(fused_kernel,
                         cudaFuncAttributeMaxDynamicSharedMemorySize, dyn_smem);

    dim3 g(L_, 2 * B_);
    fused_kernel<<<g, TPB, dyn_smem>>>(hidden, scorer, logits, ids,
                                       hte, win, dtok, n_d, (float*)d_out);
}

// round 16
// speedup vs baseline: 1.0131x; 1.0131x over previous
#include <cuda_runtime.h>

// Problem constants (fixed instance: MultiHeadAggregator_55825984913801)
#define L_    12     // layers used (hidden_states[1:])
#define B_    8
#define T_    2048
#define H_    768
#define C_    4
#define MAXNT 160    // max masked positions supported (expected: hte<=5, desc~12)
#define RCACHE 24    // rows cached in smem (fallback to global reads beyond)
#define TPB   256
#define TOKS_PER_THR (T_ / TPB)   // 8
#define NDMAX 3
#define NJ    (H_ / 4 / 16)       // 12 float4 loads per 16-lane row task

// Cross-block handshake (zero-init; self-resetting per graph replay).
__device__ volatile int g_ready[2 * B_];
__device__ int          g_cnt[2 * B_];

// ---------------------------------------------------------------------------
// SINGLE node: one block per (b, mt, l).   [FINAL — measured best: 14.82 us]
//  - the l==0 block of each bm zeroes its 12 KB out-slice FIRST (harness
//    poisons d_out), fences, and raises g_ready[bm]; other blocks only check
//    the flag right before their REDs (by then it is long set -> wait ~0).
//  - deadlock-safe: 84 KB smem / ~120 regs -> 2 blocks/SM -> all 192 blocks
//    co-resident, so the zeroing block always runs.
//  - epoch 1: ALL independent loads (ids row as coalesced int4 stride-1
//    speculative, dtype probe, dtok under both stride hypotheses, hte/win,
//    scorer_w, layer logits); deterministic order-preserving mask compaction;
//    MLP=12 staged gather with smem row cache; warp-parallel softmax with
//    layer-softmax weight folded in; RED.ADD straight into d_out.
//  - 12th arrival per bm resets flag+counter for the next replay.
// Only masked positions contribute: -1e30 masking + fp32 softmax zeroes all
// other positions exactly, so the dense reference reduces to this sparse form.
// ---------------------------------------------------------------------------
__global__ __launch_bounds__(TPB, 1)
void fused_kernel(const float* __restrict__ hidden,      // (L_+1, B, T, H)
                  const float* __restrict__ scorer_w,    // (C, H)
                  const float* __restrict__ layer_logits,// (L_)
                  const int*   __restrict__ ids32,
                  const int*   __restrict__ hte_ptr,     // low 4B of scalar
                  const int*   __restrict__ win_ptr,     // low 4B of scalar
                  const int*   __restrict__ dtok32,
                  int n_d,
                  float* __restrict__ out) {             // (B, 2, C, H)
    const int l  = blockIdx.x;          // 0..L_-1
    const int bm = blockIdx.y;          // 0..2*B_-1  (== b*2 + mt)
    const int b  = bm >> 1;
    const int mt = bm & 1;
    const int tid  = threadIdx.x;
    const int wid  = tid >> 5, lane = tid & 31;

    extern __shared__ char dsm[];
    float4* s_sc4  = (float4*)dsm;                         // 12 KB scorer
    float*  s_rows = (float*)(dsm + C_ * (H_ / 4) * 16);   // RCACHE x 768 f32

    __shared__ float  s_s[MAXNT][C_];
    __shared__ int    s_idx[MAXNT];
    __shared__ int    s_nt;
    __shared__ int    s_notzero, s_min;
    __shared__ int    s_wsum[TPB / 32], s_woff[TPB / 32];
    __shared__ float  s_lw;
    __shared__ int    s_hte, s_win;
    __shared__ int    s_d[2][NDMAX];     // dtok under stride-1 / stride-2 hypotheses

    float* op = out + (size_t)bm * (C_ * H_);

    if (tid == 0) { s_notzero = 0; s_min = 0x7fffffff; }
    __syncthreads();

    // ---- l==0 blocks: zero this bm's out-slice immediately, raise flag -----
    if (l == 0) {
        float4* op4 = (float4*)op;
        #pragma unroll
        for (int r = 0; r < 3; r++)                     // 3*256 = 768 float4
            op4[r * TPB + tid] = make_float4(0.f, 0.f, 0.f, 0.f);
        __syncthreads();
        if (tid == 0) {
            __threadfence();                            // publish zeros
            g_ready[bm] = 1;                            // release
        }
    }

    // ================= EPOCH 1: all independent loads =======================
    {   // scorer weights to smem
        const float4* sw4 = (const float4*)scorer_w;
        for (int i = tid; i < C_ * (H_ / 4); i += TPB) s_sc4[i] = sw4[i];
    }
    // speculative stride-1 token scan: 2 coalesced int4 loads per thread
    // (in-bounds under both dtype hypotheses)
    int myids[TOKS_PER_THR];
    {
        const int4* row4 = (const int4*)(ids32 + (size_t)b * T_);
        int4 v0 = row4[tid * 2];
        int4 v1 = row4[tid * 2 + 1];
        myids[0] = v0.x; myids[1] = v0.y; myids[2] = v0.z; myids[3] = v0.w;
        myids[4] = v1.x; myids[5] = v1.y; myids[6] = v1.z; myids[7] = v1.w;
    }
    if (tid < 128 && ids32[2 * tid + 1] != 0) atomicOr(&s_notzero, 1);
    if (tid == 4) s_hte = *hte_ptr;
    if (tid == 5) s_win = *win_ptr;
    if (tid >= 8  && tid < 8 + NDMAX) {           // stride-1 hypothesis
        int k = tid - 8;
        s_d[0][k] = (k < n_d) ? dtok32[k] : 0x7fffffff;
    }
    if (tid >= 12 && tid < 12 + NDMAX) {          // stride-2 hypothesis
        int k = tid - 12;
        s_d[1][k] = (k < n_d) ? dtok32[2 * k] : 0x7fffffff;
    }
    if (tid == 0) {   // layer softmax (12 elems)
        float m = -1e30f;
        #pragma unroll
        for (int k = 0; k < L_; k++) m = fmaxf(m, layer_logits[k]);
        float s = 0.f, el = 0.f;
        #pragma unroll
        for (int k = 0; k < L_; k++) {
            float e = __expf(layer_logits[k] - m);
            s += e;
            if (k == l) el = e;
        }
        s_lw = el / s;
    }
    __syncthreads();

    const int st = s_notzero ? 1 : 2;
    const int hy = s_notzero ? 0 : 1;
    if (st == 2) {  // rare path: buffer was int64 -> re-load tokens at stride 2
        const int* row2 = ids32 + (size_t)b * T_ * 2;
        #pragma unroll
        for (int j = 0; j < TOKS_PER_THR; j++)
            myids[j] = row2[(size_t)(tid * TOKS_PER_THR + j) * 2];
    }
    const int hte = s_hte;

    // ---- build mask index list for (b, mt), deterministic ------------------
    if (mt == 0) {
        int local = 0x7fffffff;
        #pragma unroll
        for (int j = 0; j < TOKS_PER_THR; j++)
            if (myids[j] == hte) local = min(local, tid * TOKS_PER_THR + j);
        if (local != 0x7fffffff) atomicMin(&s_min, local);
        __syncthreads();
        if (tid == 0) {
            int pos = (s_min == 0x7fffffff) ? (T_ - 1) : s_min;
            int hi  = pos + s_win;
            if (hi > T_ - 1) hi = T_ - 1;
            int cnt = hi - pos + 1;
            if (cnt > MAXNT) cnt = MAXNT;
            s_nt = cnt;
            for (int i = 0; i < cnt; i++) s_idx[i] = pos + i;
        }
        __syncthreads();
    } else {
        const int d0 = s_d[hy][0], d1 = s_d[hy][1], d2 = s_d[hy][2];
        int cnt = 0, loc[TOKS_PER_THR];
        #pragma unroll
        for (int j = 0; j < TOKS_PER_THR; j++) {
            int id = myids[j];
            bool isd = (id == d0) | (id == d1) | (id == d2);
            for (int k = NDMAX; k < n_d; k++) isd |= (id == dtok32[k * st]);
            if (isd) loc[cnt++] = tid * TOKS_PER_THR + j;
        }
        int inc = cnt;
        #pragma unroll
        for (int o = 1; o < 32; o <<= 1) {
            int y = __shfl_up_sync(0xffffffffu, inc, o);
            if (lane >= o) inc += y;
        }
        if (lane == 31) s_wsum[wid] = inc;
        __syncthreads();
        if (tid == 0) {
            int acc = 0;
            #pragma unroll
            for (int w = 0; w < TPB / 32; w++) { s_woff[w] = acc; acc += s_wsum[w]; }
            int total = acc;
            if (total == 0) { s_idx[0] = 0; total = 1; }
            s_nt = (total > MAXNT) ? MAXNT : total;
        }
        __syncthreads();
        int off = s_woff[wid] + inc - cnt;   // exclusive prefix
        for (int k = 0; k < cnt; k++)
            if (off + k < MAXNT) s_idx[off + k] = loc[k];
        __syncthreads();
    }
    const int nt = s_nt;

    // ================= EPOCH 2: gather, 16-lane row tasks ====================
    // Load-all-then-compute: 12 float4 staged in registers (MLP=12 -> one
    // latency epoch). Half-warp shuffle masks keep odd-nt convergence legal.
    const float*  hbase_f = hidden + (((size_t)(l + 1) * B_ + b) * T_) * H_;
    const float4* hbase   = (const float4*)hbase_f;
    {
        const int task = tid >> 4, l16 = tid & 15;         // 16 tasks x 16 lanes
        const unsigned hmask = 0xFFFFu << (lane & 16);      // my half-warp
        for (int ti = task; ti < nt; ti += 16) {
            const float4* hp = hbase + (size_t)s_idx[ti] * (H_ / 4);
            float4 xs[NJ];
            #pragma unroll
            for (int j = 0; j < NJ; j++) xs[j] = hp[j * 16 + l16];   // 12 LDG in flight
            if (ti < RCACHE) {
                float4* cache4 = (float4*)(s_rows + ti * H_);
                #pragma unroll
                for (int j = 0; j < NJ; j++) cache4[j * 16 + l16] = xs[j];
            }
            float a0 = 0.f, a1 = 0.f, a2 = 0.f, a3 = 0.f;
            #pragma unroll
            for (int j = 0; j < NJ; j++) {
                int idx = j * 16 + l16;
                float4 x  = xs[j];
                float4 w0 = s_sc4[0 * (H_ / 4) + idx];
                float4 w1 = s_sc4[1 * (H_ / 4) + idx];
                float4 w2 = s_sc4[2 * (H_ / 4) + idx];
                float4 w3 = s_sc4[3 * (H_ / 4) + idx];
                a0 = fmaf(x.x, w0.x, fmaf(x.y, w0.y, fmaf(x.z, w0.z, fmaf(x.w, w0.w, a0))));
                a1 = fmaf(x.x, w1.x, fmaf(x.y, w1.y, fmaf(x.z, w1.z, fmaf(x.w, w1.w, a1))));
                a2 = fmaf(x.x, w2.x, fmaf(x.y, w2.y, fmaf(x.z, w2.z, fmaf(x.w, w2.w, a2))));
                a3 = fmaf(x.x, w3.x, fmaf(x.y, w3.y, fmaf(x.z, w3.z, fmaf(x.w, w3.w, a3))));
            }
            #pragma unroll
            for (int o = 8; o; o >>= 1) {                  // reduce within half-warp
                a0 += __shfl_xor_sync(hmask, a0, o);
                a1 += __shfl_xor_sync(hmask, a1, o);
                a2 += __shfl_xor_sync(hmask, a2, o);
                a3 += __shfl_xor_sync(hmask, a3, o);
            }
            if (l16 == 0) {
                s_s[ti][0] = a0; s_s[ti][1] = a1; s_s[ti][2] = a2; s_s[ti][3] = a3;
            }
        }
    }
    __syncthreads();

    // ---- warp-parallel softmax: warp c per channel, lanes over positions ----
    if (wid < C_) {
        const int c = wid;
        float m = -1e30f;
        for (int i = lane; i < nt; i += 32) m = fmaxf(m, s_s[i][c]);
        #pragma unroll
        for (int o = 16; o; o >>= 1) m = fmaxf(m, __shfl_xor_sync(0xffffffffu, m, o));
        float s = 0.f;
        for (int i = lane; i < nt; i += 32) {
            float e = __expf(s_s[i][c] - m);
            s_s[i][c] = e; s += e;
        }
        #pragma unroll
        for (int o = 16; o; o >>= 1) s += __shfl_xor_sync(0xffffffffu, s, o);
        float inv = s_lw / s;
        for (int i = lane; i < nt; i += 32) s_s[i][c] *= inv;
    }

    // ---- wait for the zeroing flag (expected already set) -------------------
    __syncthreads();
    if (tid == 0) {
        while (g_ready[bm] == 0) { }        // l==0 raised it ~1 us ago
    }
    __syncthreads();                        // all threads see the zeros (acquire via fence+flag)

    // ---- this layer's contribution: RED.ADD straight into d_out ------------
    if (tid < H_ / 4) {                     // 192 threads, one float4 column each
        const int h0 = tid * 4;
        float4 a0 = {0,0,0,0}, a1 = {0,0,0,0}, a2 = {0,0,0,0}, a3 = {0,0,0,0};
        for (int i = 0; i < nt; i++) {
            float4 x = (i < RCACHE) ? *(const float4*)&s_rows[i * H_ + h0]
                                    : *(const float4*)&hbase_f[(size_t)s_idx[i] * H_ + h0];
            float w0 = s_s[i][0], w1 = s_s[i][1], w2 = s_s[i][2], w3 = s_s[i][3];
            a0.x = fmaf(w0, x.x, a0.x); a0.y = fmaf(w0, x.y, a0.y); a0.z = fmaf(w0, x.z, a0.z); a0.w = fmaf(w0, x.w, a0.w);
            a1.x = fmaf(w1, x.x, a1.x); a1.y = fmaf(w1, x.y, a1.y); a1.z = fmaf(w1, x.z, a1.z); a1.w = fmaf(w1, x.w, a1.w);
            a2.x = fmaf(w2, x.x, a2.x); a2.y = fmaf(w2, x.y, a2.y); a2.z = fmaf(w2, x.z, a2.z); a2.w = fmaf(w2, x.w, a2.w);
            a3.x = fmaf(w3, x.x, a3.x); a3.y = fmaf(w3, x.y, a3.y); a3.z = fmaf(w3, x.z, a3.z); a3.w = fmaf(w3, x.w, a3.w);
        }
        atomicAdd(&op[0 * H_ + h0 + 0], a0.x); atomicAdd(&op[0 * H_ + h0 + 1], a0.y);
        atomicAdd(&op[0 * H_ + h0 + 2], a0.z); atomicAdd(&op[0 * H_ + h0 + 3], a0.w);
        atomicAdd(&op[1 * H_ + h0 + 0], a1.x); atomicAdd(&op[1 * H_ + h0 + 1], a1.y);
        atomicAdd(&op[1 * H_ + h0 + 2], a1.z); atomicAdd(&op[1 * H_ + h0 + 3], a1.w);
        atomicAdd(&op[2 * H_ + h0 + 0], a2.x); atomicAdd(&op[2 * H_ + h0 + 1], a2.y);
        atomicAdd(&op[2 * H_ + h0 + 2], a2.z); atomicAdd(&op[2 * H_ + h0 + 3], a2.w);
        atomicAdd(&op[3 * H_ + h0 + 0], a3.x); atomicAdd(&op[3 * H_ + h0 + 1], a3.y);
        atomicAdd(&op[3 * H_ + h0 + 2], a3.z); atomicAdd(&op[3 * H_ + h0 + 3], a3.w);
    }

    // ---- self-reset for the next graph replay ------------------------------
    __syncthreads();                        // my REDs issued
    if (tid == 0) {
        int old = atomicAdd(&g_cnt[bm], 1);
        if (old == L_ - 1) {                // 12th arrival: everyone passed the spin
            g_cnt[bm] = 0;
            g_ready[bm] = 0;
        }
    }
}

// ---------------------------------------------------------------------------
extern "C" void kernel_launch(void* const* d_in, const int* in_sizes, int n_in,
                              void* d_out, int out_size) {
    const float* hidden = (const float*)d_in[0];
    const int*   ids    = (const int*)d_in[1];
    const float* logits = (const float*)d_in[2];
    const float* scorer = (const float*)d_in[3];
    const int*   hte    = (const int*)d_in[4];   // low 4B valid for i32/i64 small values
    const int*   dtok   = (const int*)d_in[5];
    const int*   win    = (const int*)d_in[6];
    const int n_d = in_sizes[5];

    const int dyn_smem = C_ * (H_ / 4) * 16 + RCACHE * H_ * 4;  // 12 KB + 72 KB
    cudaFuncSetAttribute(fused_kernel,
                         cudaFuncAttributeMaxDynamicSharedMemorySize, dyn_smem);

    dim3 g(L_, 2 * B_);
    fused_kernel<<<g, TPB, dyn_smem>>>(hidden, scorer, logits, ids,
                                       hte, win, dtok, n_d, (float*)d_out);
}